// round 1
// baseline (speedup 1.0000x reference)
#include <cuda_runtime.h>
#include <math.h>

// Problem dims
#define NB   131072
#define S_D  376
#define H1_D 400
#define H2_D 300
#define A_D  17
#define M_D  5
#define O3_D 255   // 3*A*M

#define EPIS_MIN 4.53999297624848e-05f
#define EPIS_MAX 7.38905609893065f
// 0.5 * 17 * log(2*pi)
#define HALF_D_LOG2PI 15.6219550644794f

// Scratch (allocation-free rule: __device__ globals). g_buf1 reused for layer-3 logits.
__device__ float g_buf1[(size_t)NB * H1_D];   // h1, then z3 (stride 255)
__device__ float g_buf2[(size_t)NB * H2_D];   // h2

// ---------------------------------------------------------------------------
// Tiled SGEMM: C[M,N] = act(A[M,K] @ W[K,N] + bias[N])
// BM=BN=128, BK=8, 256 threads, 8x8 micro-tile per thread (split 4+4).
// ACT: 0 = ReLU, 1 = none (store raw)
// M (=NB) is always a multiple of 128; N,K handled with guards / zero-pad.
// ---------------------------------------------------------------------------
template<int ACT>
__global__ __launch_bounds__(256, 2)
void gemm_kernel(const float* __restrict__ A, const float* __restrict__ W,
                 const float* __restrict__ bias, float* __restrict__ C,
                 int N, int K)
{
    __shared__ float As[8][132];   // [k][row], padded vs bank conflicts
    __shared__ float Bs[8][132];   // [k][col]

    const int tid  = threadIdx.x;
    const int tx   = tid & 15;     // col group 0..15
    const int ty   = tid >> 4;     // row group 0..15
    const int row0 = blockIdx.y * 128;
    const int col0 = blockIdx.x * 128;

    float acc[8][8];
    #pragma unroll
    for (int i = 0; i < 8; i++)
        #pragma unroll
        for (int j = 0; j < 8; j++) acc[i][j] = 0.f;

    // A-load mapping: lane covers (row=tid/8 + 32*it, k=tid%8)
    const int lk = tid & 7;
    const int lr = tid >> 3;
    // B-load mapping: lane covers (k=tid/128 + 2*it, col=tid%128)
    const int bk = tid >> 7;
    const int bn = tid & 127;

    for (int k0 = 0; k0 < K; k0 += 8) {
        #pragma unroll
        for (int it = 0; it < 4; it++) {
            int r  = lr + it * 32;
            int kk = k0 + lk;
            float v = 0.f;
            if (kk < K) v = A[(size_t)(row0 + r) * K + kk];
            As[lk][r] = v;
        }
        #pragma unroll
        for (int it = 0; it < 4; it++) {
            int kk = k0 + bk + it * 2;
            float v = 0.f;
            if (kk < K && (col0 + bn) < N) v = W[(size_t)kk * N + col0 + bn];
            Bs[bk + it * 2][bn] = v;
        }
        __syncthreads();

        #pragma unroll
        for (int k = 0; k < 8; k++) {
            float a[8], b[8];
            *(float4*)&a[0] = *(const float4*)&As[k][ty * 4];
            *(float4*)&a[4] = *(const float4*)&As[k][64 + ty * 4];
            *(float4*)&b[0] = *(const float4*)&Bs[k][tx * 4];
            *(float4*)&b[4] = *(const float4*)&Bs[k][64 + tx * 4];
            #pragma unroll
            for (int i = 0; i < 8; i++)
                #pragma unroll
                for (int j = 0; j < 8; j++)
                    acc[i][j] = fmaf(a[i], b[j], acc[i][j]);
        }
        __syncthreads();
    }

    #pragma unroll
    for (int i = 0; i < 8; i++) {
        int r = row0 + ((i < 4) ? (ty * 4 + i) : (64 + ty * 4 + i - 4));
        #pragma unroll
        for (int j = 0; j < 8; j++) {
            int c = col0 + ((j < 4) ? (tx * 4 + j) : (64 + tx * 4 + j - 4));
            if (c < N) {
                float v = acc[i][j] + bias[c];
                if (ACT == 0) v = fmaxf(v, 0.f);
                C[(size_t)r * N + c] = v;
            }
        }
    }
}

// Cancellation-safe fast tanh: abs error ~1e-7 (exp-based; (1-e)/(1+e) form).
__device__ __forceinline__ float fast_tanh(float x)
{
    float ax = fabsf(x);
    float e  = __expf(-2.f * ax);
    float t  = __fdividef(1.f - e, 1.f + e);
    return copysignf(t, x);
}

// ---------------------------------------------------------------------------
// Epilogue: one warp per row. Lanes 0..16 handle one action each.
// Reads raw layer-3 logits z3[row][255]; writes tanh_sample, log_pi_ttl/eps.
// ---------------------------------------------------------------------------
__global__ __launch_bounds__(256)
void epilogue_kernel(const float* __restrict__ z3, const float* __restrict__ eps,
                     float* __restrict__ out)
{
    int gwarp = (blockIdx.x * blockDim.x + threadIdx.x) >> 5;
    int lane  = threadIdx.x & 31;
    if (gwarp >= NB) return;

    const float* L = z3 + (size_t)gwarp * O3_D;

    float term_ttl = 0.f, term_eps = 0.f, corr = 0.f;

    if (lane < A_D) {
        int a = lane;
        float mw[M_D], mm[M_D], lms[M_D];
        #pragma unroll
        for (int m = 0; m < M_D; m++) {
            mw[m]  = fast_tanh(L[a * M_D + m]);
            mm[m]  = fast_tanh(L[85 + a * M_D + m]);
            lms[m] = fast_tanh(L[170 + a * M_D + m]);
        }
        // softmax over mixtures
        float mx = mw[0];
        #pragma unroll
        for (int m = 1; m < M_D; m++) mx = fmaxf(mx, mw[m]);
        float e[M_D], se = 0.f;
        #pragma unroll
        for (int m = 0; m < M_D; m++) { e[m] = __expf(mw[m] - mx); se += e[m]; }
        float inv = __fdividef(1.f, se);

        float mean = 0.f, alea = 0.f;
        float w[M_D];
        #pragma unroll
        for (int m = 0; m < M_D; m++) {
            w[m]  = e[m] * inv;
            mean += w[m] * mm[m];
            float lc = fminf(fmaxf(lms[m], -10.f), 2.f);
            alea += w[m] * __expf(lc);
        }
        float epis = 0.f;
        #pragma unroll
        for (int m = 0; m < M_D; m++) {
            float d = mm[m] - mean;
            epis += w[m] * d * d;
        }
        epis = fminf(fmaxf(epis, EPIS_MIN), EPIS_MAX);
        float total = alea + epis;

        float ev = eps[(size_t)gwarp * A_D + a];
        float x  = mean + total * ev;          // rsample
        float th = fast_tanh(x);
        out[(size_t)gwarp * A_D + a] = th;

        float d  = x - mean;
        float zt = __fdividef(d, total);
        float ze = __fdividef(d, epis);
        term_ttl = zt * zt + 2.f * __logf(total);
        term_eps = ze * ze + 2.f * __logf(epis);
        corr     = __logf(1.f - th * th + 1e-6f);
    }

    #pragma unroll
    for (int off = 16; off > 0; off >>= 1) {
        term_ttl += __shfl_down_sync(0xffffffffu, term_ttl, off);
        term_eps += __shfl_down_sync(0xffffffffu, term_eps, off);
        corr     += __shfl_down_sync(0xffffffffu, corr, off);
    }

    if (lane == 0) {
        float lp_ttl = -0.5f * term_ttl - HALF_D_LOG2PI;
        float lp_eps = -0.5f * term_eps - HALF_D_LOG2PI;
        out[(size_t)NB * A_D + gwarp]        = lp_ttl - corr;
        out[(size_t)NB * (A_D + 1) + gwarp]  = lp_eps - corr;
    }
}

extern "C" void kernel_launch(void* const* d_in, const int* in_sizes, int n_in,
                              void* d_out, int out_size)
{
    (void)in_sizes; (void)n_in; (void)out_size;
    const float* state = (const float*)d_in[0];
    const float* eps   = (const float*)d_in[1];
    const float* W1    = (const float*)d_in[2];
    const float* b1    = (const float*)d_in[3];
    const float* W2    = (const float*)d_in[4];
    const float* b2    = (const float*)d_in[5];
    const float* W3    = (const float*)d_in[6];
    const float* b3    = (const float*)d_in[7];
    float* out = (float*)d_out;

    void *p1, *p2;
    cudaGetSymbolAddress(&p1, g_buf1);
    cudaGetSymbolAddress(&p2, g_buf2);
    float* h1 = (float*)p1;
    float* h2 = (float*)p2;
    float* z3 = (float*)p1;   // reuse buf1 for layer-3 logits (stride 255)

    dim3 blk(256);
    dim3 g1((H1_D + 127) / 128, NB / 128);
    dim3 g2((H2_D + 127) / 128, NB / 128);
    dim3 g3((O3_D + 127) / 128, NB / 128);

    gemm_kernel<0><<<g1, blk>>>(state, W1, b1, h1, H1_D, S_D);
    gemm_kernel<0><<<g2, blk>>>(h1,    W2, b2, h2, H2_D, H1_D);
    gemm_kernel<1><<<g3, blk>>>(h2,    W3, b3, z3, O3_D, H2_D);

    // one warp per row
    int rows_per_block = 256 / 32;
    dim3 ge(NB / rows_per_block);
    epilogue_kernel<<<ge, blk>>>(z3, eps, out);
}

// round 3
// speedup vs baseline: 1.7480x; 1.7480x over previous
#include <cuda_runtime.h>
#include <cuda_bf16.h>
#include <math.h>
#include <stdint.h>

// ---------------- problem dims ----------------
#define NB   131072
#define A_D  17
#define M_D  5

#define K1   376      // state dim
#define N1   400
#define N2   300
#define K1P  384      // 12 chunks of 32
#define K2P  416      // 13 chunks
#define K3P  320      // 10 chunks

#define EPIS_MIN 4.53999297624848e-05f
#define EPIS_MAX 7.38905609893065f
#define HALF_D_LOG2PI 15.6219550644794f

// ---------------- scratch (__device__ globals) ----------------
// activations pre-split to bf16 hi/lo, row stride = next layer's padded K
__device__ __align__(16) __nv_bfloat16 g_h1hi[(size_t)NB * K2P];
__device__ __align__(16) __nv_bfloat16 g_h1lo[(size_t)NB * K2P];
__device__ __align__(16) __nv_bfloat16 g_h2hi[(size_t)NB * K3P];
__device__ __align__(16) __nv_bfloat16 g_h2lo[(size_t)NB * K3P];
__device__ __align__(16) float g_z3[(size_t)NB * 256];

// weights, transposed + split: [N_alloc][K_pad], zero-padded
__device__ __align__(16) __nv_bfloat16 g_w1hi[512 * K1P], g_w1lo[512 * K1P];
__device__ __align__(16) __nv_bfloat16 g_w2hi[384 * K2P], g_w2lo[384 * K2P];
__device__ __align__(16) __nv_bfloat16 g_w3hi[256 * K3P], g_w3lo[256 * K3P];

// ---------------- helpers ----------------
__device__ __forceinline__ uint32_t smem_u32(const void* p) {
    uint32_t a;
    asm("{ .reg .u64 t; cvta.to.shared.u64 t, %1; cvt.u32.u64 %0, t; }" : "=r"(a) : "l"(p));
    return a;
}

__device__ __forceinline__ void ldsm4(uint32_t* r, uint32_t addr) {
    asm volatile("ldmatrix.sync.aligned.m8n8.x4.shared.b16 {%0,%1,%2,%3}, [%4];"
                 : "=r"(r[0]), "=r"(r[1]), "=r"(r[2]), "=r"(r[3]) : "r"(addr));
}

__device__ __forceinline__ void mma_bf16(float* c, const uint32_t* a, const uint32_t* b) {
    asm volatile("mma.sync.aligned.m16n8k16.row.col.f32.bf16.bf16.f32 "
                 "{%0,%1,%2,%3}, {%4,%5,%6,%7}, {%8,%9}, {%0,%1,%2,%3};"
                 : "+f"(c[0]), "+f"(c[1]), "+f"(c[2]), "+f"(c[3])
                 : "r"(a[0]), "r"(a[1]), "r"(a[2]), "r"(a[3]), "r"(b[0]), "r"(b[1]));
}

__device__ __forceinline__ void cp16(uint32_t dst, const void* src, int ssize) {
    asm volatile("cp.async.cg.shared.global [%0], [%1], 16, %2;"
                 :: "r"(dst), "l"(src), "r"(ssize) : "memory");
}
#define CP_COMMIT() asm volatile("cp.async.commit_group;" ::: "memory")
#define CP_WAIT1()  asm volatile("cp.async.wait_group 1;" ::: "memory")

__device__ __forceinline__ void split_bf16(float x, __nv_bfloat16& h, __nv_bfloat16& l) {
    h = __float2bfloat16_rn(x);
    l = __float2bfloat16_rn(x - __bfloat162float(h));
}
__device__ __forceinline__ uint32_t pack_us(__nv_bfloat16 a, __nv_bfloat16 b) {
    return (uint32_t)__bfloat16_as_ushort(a) | ((uint32_t)__bfloat16_as_ushort(b) << 16);
}

// ---------------- weight prep: transpose + bf16 hi/lo split ----------------
__global__ void split_w(const float* __restrict__ W, __nv_bfloat16* __restrict__ Hh,
                        __nv_bfloat16* __restrict__ Hl, int K, int N, int Kp, int total)
{
    int idx = blockIdx.x * blockDim.x + threadIdx.x;
    if (idx >= total) return;
    int n = idx / Kp;
    int k = idx - n * Kp;
    float v = (k < K && n < N) ? W[(size_t)k * N + n] : 0.f;
    __nv_bfloat16 h, l;
    split_bf16(v, h, l);
    Hh[idx] = h;
    Hl[idx] = l;
}

// ---------------- bf16x3 mma GEMM ----------------
// BM=128, BN=128, BK=32; 8 warps (2 row-groups x 4 col-groups), warp tile 64x32.
// smem: per stage, 4 arrays of 128 rows x 32 bf16 @ 80B pitch (conflict-free ldmatrix).
#define ST_SZ  40960
#define AHI_O  0
#define ALO_O  10240
#define BHI_O  20480
#define BLO_O  30720
#define SMEM_TOT (2 * ST_SZ)

template<int A_PRE, int OUT_BF16>
__global__ __launch_bounds__(256, 1)
void mma_gemm(const float* __restrict__ Af,
              const __nv_bfloat16* __restrict__ Ah, const __nv_bfloat16* __restrict__ Al,
              int sA,
              const __nv_bfloat16* __restrict__ Bh, const __nv_bfloat16* __restrict__ Bl,
              const float* __restrict__ bias,
              float* __restrict__ Cf, __nv_bfloat16* __restrict__ Ch, __nv_bfloat16* __restrict__ Cl,
              int K, int nch, int N, int Nbias, int sC)
{
    extern __shared__ char smem[];
    const uint32_t sb = smem_u32(smem);
    const int tid  = threadIdx.x;
    const int lane = tid & 31;
    const int wid  = tid >> 5;
    const int wrow = wid & 1;        // 0..1 : 64-row group
    const int wcol = wid >> 1;       // 0..3 : 32-col group
    const int row0 = blockIdx.y * 128;
    const int col0 = blockIdx.x * 128;
    const int extw = (N - col0) - wcol * 32;
    const int live_nt = max(0, min(4, (extw + 7) >> 3));

    const int lr  = tid >> 1;        // 0..127 (row within tile)
    const int lo2 = (tid & 1) * 32;  // byte offset within 64B row-chunk

    float acc[4][4][4];
    #pragma unroll
    for (int i = 0; i < 4; i++)
        #pragma unroll
        for (int j = 0; j < 4; j++)
            #pragma unroll
            for (int q = 0; q < 4; q++) acc[i][j][q] = 0.f;

    auto load_chunk = [&](int c, int s) {
        const uint32_t stb = sb + s * ST_SZ;
        const uint32_t drow = stb + lr * 80 + lo2;
        // B: fully zero-padded in gmem, no guards
        {
            size_t g = (size_t)(col0 + lr) * (nch * 32) + c * 32 + (lo2 >> 1);
            cp16(drow + BHI_O,      Bh + g,     16);
            cp16(drow + BHI_O + 16, Bh + g + 8, 16);
            cp16(drow + BLO_O,      Bl + g,     16);
            cp16(drow + BLO_O + 16, Bl + g + 8, 16);
        }
        if (A_PRE) {
            int k0 = c * 32 + (lo2 >> 1);
            size_t g = (size_t)(row0 + lr) * sA + k0;
            int s0 = min(16, max(0, (K - k0) * 2));
            int s1 = min(16, max(0, (K - (k0 + 8)) * 2));
            cp16(drow + AHI_O,      Ah + g,     s0);
            cp16(drow + AHI_O + 16, Ah + g + 8, s1);
            cp16(drow + ALO_O,      Al + g,     s0);
            cp16(drow + ALO_O + 16, Al + g + 8, s1);
        } else {
            // fp32 A: load, split, store (16 elems/thread)
            const int akh = (tid & 1) * 16;
            uint32_t hw[8], lw[8];
            #pragma unroll
            for (int i = 0; i < 4; ++i) {
                int k = c * 32 + akh + i * 4;
                float4 v = make_float4(0.f, 0.f, 0.f, 0.f);
                if (k < K) v = *(const float4*)(Af + (size_t)(row0 + lr) * K + k);
                __nv_bfloat16 h0, l0, h1, l1;
                split_bf16(v.x, h0, l0); split_bf16(v.y, h1, l1);
                hw[i*2]   = pack_us(h0, h1); lw[i*2]   = pack_us(l0, l1);
                split_bf16(v.z, h0, l0); split_bf16(v.w, h1, l1);
                hw[i*2+1] = pack_us(h0, h1); lw[i*2+1] = pack_us(l0, l1);
            }
            char* d = smem + s * ST_SZ + lr * 80 + akh * 2;
            *(uint4*)(d + AHI_O)      = make_uint4(hw[0], hw[1], hw[2], hw[3]);
            *(uint4*)(d + AHI_O + 16) = make_uint4(hw[4], hw[5], hw[6], hw[7]);
            *(uint4*)(d + ALO_O)      = make_uint4(lw[0], lw[1], lw[2], lw[3]);
            *(uint4*)(d + ALO_O + 16) = make_uint4(lw[4], lw[5], lw[6], lw[7]);
        }
    };

    load_chunk(0, 0);
    CP_COMMIT();

    for (int c = 0; c < nch; ++c) {
        if (c + 1 < nch) load_chunk(c + 1, (c + 1) & 1);
        CP_COMMIT();
        CP_WAIT1();
        __syncthreads();

        const uint32_t stb = sb + (c & 1) * ST_SZ;
        #pragma unroll
        for (int ks = 0; ks < 2; ++ks) {
            uint32_t bh[8], bl[8];
            #pragma unroll
            for (int p = 0; p < 2; ++p) {
                uint32_t n = wcol * 32 + p * 16 + (lane & 7) + ((lane >> 4) << 3);
                uint32_t off = n * 80 + ((lane >> 3) & 1) * 16 + ks * 32;
                ldsm4(&bh[p * 4], stb + BHI_O + off);
                ldsm4(&bl[p * 4], stb + BLO_O + off);
            }
            #pragma unroll
            for (int mt = 0; mt < 4; ++mt) {
                uint32_t r = wrow * 64 + mt * 16 + (lane & 15);
                uint32_t off = r * 80 + ((lane >> 4) << 4) + ks * 32;
                uint32_t ah[4], al[4];
                ldsm4(ah, stb + AHI_O + off);
                ldsm4(al, stb + ALO_O + off);
                #pragma unroll
                for (int nt = 0; nt < 4; ++nt) {
                    if (nt < live_nt) {
                        mma_bf16(acc[mt][nt], ah, &bh[nt * 2]);
                        mma_bf16(acc[mt][nt], ah, &bl[nt * 2]);
                        mma_bf16(acc[mt][nt], al, &bh[nt * 2]);
                    }
                }
            }
        }
        __syncthreads();
    }

    // ---- store ----
    #pragma unroll
    for (int mt = 0; mt < 4; ++mt) {
        int r0 = row0 + wrow * 64 + mt * 16 + (lane >> 2);
        int r1 = r0 + 8;
        #pragma unroll
        for (int nt = 0; nt < 4; ++nt) {
            int col = col0 + wcol * 32 + nt * 8 + (lane & 3) * 2;
            if (OUT_BF16) {
                if (col < N) {
                    float b0 = bias[col], b1 = bias[col + 1];
                    float v00 = fmaxf(acc[mt][nt][0] + b0, 0.f);
                    float v01 = fmaxf(acc[mt][nt][1] + b1, 0.f);
                    float v10 = fmaxf(acc[mt][nt][2] + b0, 0.f);
                    float v11 = fmaxf(acc[mt][nt][3] + b1, 0.f);
                    __nv_bfloat16 h0, l0, h1, l1;
                    split_bf16(v00, h0, l0); split_bf16(v01, h1, l1);
                    *(uint32_t*)(Ch + (size_t)r0 * sC + col) = pack_us(h0, h1);
                    *(uint32_t*)(Cl + (size_t)r0 * sC + col) = pack_us(l0, l1);
                    split_bf16(v10, h0, l0); split_bf16(v11, h1, l1);
                    *(uint32_t*)(Ch + (size_t)r1 * sC + col) = pack_us(h0, h1);
                    *(uint32_t*)(Cl + (size_t)r1 * sC + col) = pack_us(l0, l1);
                }
            } else {
                float b0 = (col < Nbias) ? bias[col] : 0.f;
                float b1 = (col + 1 < Nbias) ? bias[col + 1] : 0.f;
                float2 p0 = make_float2(acc[mt][nt][0] + b0, acc[mt][nt][1] + b1);
                float2 p1 = make_float2(acc[mt][nt][2] + b0, acc[mt][nt][3] + b1);
                *(float2*)(Cf + (size_t)r0 * sC + col) = p0;
                *(float2*)(Cf + (size_t)r1 * sC + col) = p1;
            }
        }
    }
}

// ---------------- math epilogue ----------------
__device__ __forceinline__ float fast_tanh(float x)
{
    float ax = fabsf(x);
    float e  = __expf(-2.f * ax);
    float t  = __fdividef(1.f - e, 1.f + e);
    return copysignf(t, x);
}

__global__ __launch_bounds__(256)
void epilogue_kernel(const float* __restrict__ z3, const float* __restrict__ eps,
                     float* __restrict__ out)
{
    int gwarp = (blockIdx.x * blockDim.x + threadIdx.x) >> 5;
    int lane  = threadIdx.x & 31;
    if (gwarp >= NB) return;

    const float* L = z3 + (size_t)gwarp * 256;

    float term_ttl = 0.f, term_eps = 0.f, corr = 0.f;

    if (lane < A_D) {
        int a = lane;
        float mw[M_D], mm[M_D], lms[M_D];
        #pragma unroll
        for (int m = 0; m < M_D; m++) {
            mw[m]  = fast_tanh(L[a * M_D + m]);
            mm[m]  = fast_tanh(L[85 + a * M_D + m]);
            lms[m] = fast_tanh(L[170 + a * M_D + m]);
        }
        float mx = mw[0];
        #pragma unroll
        for (int m = 1; m < M_D; m++) mx = fmaxf(mx, mw[m]);
        float e[M_D], se = 0.f;
        #pragma unroll
        for (int m = 0; m < M_D; m++) { e[m] = __expf(mw[m] - mx); se += e[m]; }
        float inv = __fdividef(1.f, se);

        float mean = 0.f, alea = 0.f;
        float w[M_D];
        #pragma unroll
        for (int m = 0; m < M_D; m++) {
            w[m]  = e[m] * inv;
            mean += w[m] * mm[m];
            float lc = fminf(fmaxf(lms[m], -10.f), 2.f);
            alea += w[m] * __expf(lc);
        }
        float epis = 0.f;
        #pragma unroll
        for (int m = 0; m < M_D; m++) {
            float dd = mm[m] - mean;
            epis += w[m] * dd * dd;
        }
        epis = fminf(fmaxf(epis, EPIS_MIN), EPIS_MAX);
        float total = alea + epis;

        float ev = eps[(size_t)gwarp * A_D + a];
        float x  = mean + total * ev;
        float th = fast_tanh(x);
        out[(size_t)gwarp * A_D + a] = th;

        float d  = x - mean;
        float zt = __fdividef(d, total);
        float ze = __fdividef(d, epis);
        term_ttl = zt * zt + 2.f * __logf(total);
        term_eps = ze * ze + 2.f * __logf(epis);
        corr     = __logf(1.f - th * th + 1e-6f);
    }

    #pragma unroll
    for (int off = 16; off > 0; off >>= 1) {
        term_ttl += __shfl_down_sync(0xffffffffu, term_ttl, off);
        term_eps += __shfl_down_sync(0xffffffffu, term_eps, off);
        corr     += __shfl_down_sync(0xffffffffu, corr, off);
    }

    if (lane == 0) {
        float lp_ttl = -0.5f * term_ttl - HALF_D_LOG2PI;
        float lp_eps = -0.5f * term_eps - HALF_D_LOG2PI;
        out[(size_t)NB * A_D + gwarp]       = lp_ttl - corr;
        out[(size_t)NB * (A_D + 1) + gwarp] = lp_eps - corr;
    }
}

// ---------------- launch ----------------
extern "C" void kernel_launch(void* const* d_in, const int* in_sizes, int n_in,
                              void* d_out, int out_size)
{
    (void)in_sizes; (void)n_in; (void)out_size;
    const float* state = (const float*)d_in[0];
    const float* eps   = (const float*)d_in[1];
    const float* W1    = (const float*)d_in[2];
    const float* b1    = (const float*)d_in[3];
    const float* W2    = (const float*)d_in[4];
    const float* b2    = (const float*)d_in[5];
    const float* W3    = (const float*)d_in[6];
    const float* b3    = (const float*)d_in[7];
    float* out = (float*)d_out;

    void *p;
    cudaGetSymbolAddress(&p, g_h1hi); __nv_bfloat16* h1h = (__nv_bfloat16*)p;
    cudaGetSymbolAddress(&p, g_h1lo); __nv_bfloat16* h1l = (__nv_bfloat16*)p;
    cudaGetSymbolAddress(&p, g_h2hi); __nv_bfloat16* h2h = (__nv_bfloat16*)p;
    cudaGetSymbolAddress(&p, g_h2lo); __nv_bfloat16* h2l = (__nv_bfloat16*)p;
    cudaGetSymbolAddress(&p, g_z3);   float* z3 = (float*)p;
    cudaGetSymbolAddress(&p, g_w1hi); __nv_bfloat16* w1h = (__nv_bfloat16*)p;
    cudaGetSymbolAddress(&p, g_w1lo); __nv_bfloat16* w1l = (__nv_bfloat16*)p;
    cudaGetSymbolAddress(&p, g_w2hi); __nv_bfloat16* w2h = (__nv_bfloat16*)p;
    cudaGetSymbolAddress(&p, g_w2lo); __nv_bfloat16* w2l = (__nv_bfloat16*)p;
    cudaGetSymbolAddress(&p, g_w3hi); __nv_bfloat16* w3h = (__nv_bfloat16*)p;
    cudaGetSymbolAddress(&p, g_w3lo); __nv_bfloat16* w3l = (__nv_bfloat16*)p;

    cudaFuncSetAttribute(mma_gemm<0,1>, cudaFuncAttributeMaxDynamicSharedMemorySize, SMEM_TOT);
    cudaFuncSetAttribute(mma_gemm<1,1>, cudaFuncAttributeMaxDynamicSharedMemorySize, SMEM_TOT);
    cudaFuncSetAttribute(mma_gemm<1,0>, cudaFuncAttributeMaxDynamicSharedMemorySize, SMEM_TOT);

    // weight prep
    split_w<<<(512 * K1P + 255) / 256, 256>>>(W1, w1h, w1l, K1,  N1,  K1P, 512 * K1P);
    split_w<<<(384 * K2P + 255) / 256, 256>>>(W2, w2h, w2l, N1,  N2,  K2P, 384 * K2P);
    split_w<<<(256 * K3P + 255) / 256, 256>>>(W3, w3h, w3l, N2,  255, K3P, 256 * K3P);

    dim3 blk(256);
    // L1: A=state fp32 (split in-kernel), out bf16 h1 (stride K2P), relu
    mma_gemm<0,1><<<dim3(4, NB/128), blk, SMEM_TOT>>>(
        state, nullptr, nullptr, 0, w1h, w1l, b1,
        nullptr, h1h, h1l, K1, 12, N1, N1, K2P);
    // L2: A=h1 pre-split, out bf16 h2 (stride K3P), relu
    mma_gemm<1,1><<<dim3(3, NB/128), blk, SMEM_TOT>>>(
        nullptr, h1h, h1l, K2P, w2h, w2l, b2,
        nullptr, h2h, h2l, N1, 13, N2, N2, K3P);
    // L3: A=h2 pre-split, out fp32 z3 (stride 256), raw
    mma_gemm<1,0><<<dim3(2, NB/128), blk, SMEM_TOT>>>(
        nullptr, h2h, h2l, K3P, w3h, w3l, b3,
        z3, nullptr, nullptr, N2, 10, 256, 255, 256);

    epilogue_kernel<<<NB/8, 256>>>(z3, eps, out);
}

// round 4
// speedup vs baseline: 1.9441x; 1.1122x over previous
#include <cuda_runtime.h>
#include <cuda_bf16.h>
#include <math.h>
#include <stdint.h>

// ---------------- problem dims ----------------
#define NB   131072
#define A_D  17
#define M_D  5

#define K1   376      // state dim
#define N1   400
#define N2   300
#define K1P  384      // 12 chunks of 32
#define K2P  416      // 13 chunks
#define K3P  320      // 10 chunks

#define EPIS_MIN 4.53999297624848e-05f
#define EPIS_MAX 7.38905609893065f
#define HALF_D_LOG2PI 15.6219550644794f

// ---------------- scratch (__device__ globals) ----------------
__device__ __align__(16) __nv_bfloat16 g_h1hi[(size_t)NB * K2P];
__device__ __align__(16) __nv_bfloat16 g_h1lo[(size_t)NB * K2P];
__device__ __align__(16) __nv_bfloat16 g_h2hi[(size_t)NB * K3P];
__device__ __align__(16) __nv_bfloat16 g_h2lo[(size_t)NB * K3P];
__device__ __align__(16) float g_z3[(size_t)NB * 256];

// weights, transposed + split: [N_alloc][K_pad], zero-padded
__device__ __align__(16) __nv_bfloat16 g_w1hi[512 * K1P], g_w1lo[512 * K1P];
__device__ __align__(16) __nv_bfloat16 g_w2hi[384 * K2P], g_w2lo[384 * K2P];
__device__ __align__(16) __nv_bfloat16 g_w3hi[256 * K3P], g_w3lo[256 * K3P];

// ---------------- helpers ----------------
__device__ __forceinline__ uint32_t smem_u32(const void* p) {
    uint32_t a;
    asm("{ .reg .u64 t; cvta.to.shared.u64 t, %1; cvt.u32.u64 %0, t; }" : "=r"(a) : "l"(p));
    return a;
}

__device__ __forceinline__ void ldsm4(uint32_t* r, uint32_t addr) {
    asm volatile("ldmatrix.sync.aligned.m8n8.x4.shared.b16 {%0,%1,%2,%3}, [%4];"
                 : "=r"(r[0]), "=r"(r[1]), "=r"(r[2]), "=r"(r[3]) : "r"(addr));
}

__device__ __forceinline__ void mma_bf16(float* c, const uint32_t* a, const uint32_t* b) {
    asm volatile("mma.sync.aligned.m16n8k16.row.col.f32.bf16.bf16.f32 "
                 "{%0,%1,%2,%3}, {%4,%5,%6,%7}, {%8,%9}, {%0,%1,%2,%3};"
                 : "+f"(c[0]), "+f"(c[1]), "+f"(c[2]), "+f"(c[3])
                 : "r"(a[0]), "r"(a[1]), "r"(a[2]), "r"(a[3]), "r"(b[0]), "r"(b[1]));
}

__device__ __forceinline__ void cp16(uint32_t dst, const void* src, int ssize) {
    asm volatile("cp.async.cg.shared.global [%0], [%1], 16, %2;"
                 :: "r"(dst), "l"(src), "r"(ssize) : "memory");
}
#define CP_COMMIT() asm volatile("cp.async.commit_group;" ::: "memory")
#define CP_WAIT1()  asm volatile("cp.async.wait_group 1;" ::: "memory")

__device__ __forceinline__ void split_bf16(float x, __nv_bfloat16& h, __nv_bfloat16& l) {
    h = __float2bfloat16_rn(x);
    l = __float2bfloat16_rn(x - __bfloat162float(h));
}
__device__ __forceinline__ uint32_t pack_us(__nv_bfloat16 a, __nv_bfloat16 b) {
    return (uint32_t)__bfloat16_as_ushort(a) | ((uint32_t)__bfloat16_as_ushort(b) << 16);
}

// ---------------- weight prep: transpose + bf16 hi/lo split ----------------
__global__ void split_w(const float* __restrict__ W, __nv_bfloat16* __restrict__ Hh,
                        __nv_bfloat16* __restrict__ Hl, int K, int N, int Kp, int total)
{
    int idx = blockIdx.x * blockDim.x + threadIdx.x;
    if (idx >= total) return;
    int n = idx / Kp;
    int k = idx - n * Kp;
    float v = (k < K && n < N) ? W[(size_t)k * N + n] : 0.f;
    __nv_bfloat16 h, l;
    split_bf16(v, h, l);
    Hh[idx] = h;
    Hl[idx] = l;
}

// ---------------- bf16x3 mma GEMM ----------------
// BM=128, BN=64, BK=32; 8 warps as 4(row)x2(col); warp tile 32x32.
// 3-stage cp.async pipeline (lookahead 2), one __syncthreads per chunk.
// smem rows: 32 bf16 @ 80B pitch (conflict-free ldmatrix).
#define AHI_O  0
#define ALO_O  10240
#define BHI_O  20480
#define BLO_O  25600
#define ST_SZ  30720
#define SMEM_TOT (3 * ST_SZ)

template<int A_PRE, int OUT_BF16>
__global__ __launch_bounds__(256, 2)
void mma_gemm(const float* __restrict__ Af,
              const __nv_bfloat16* __restrict__ Ah, const __nv_bfloat16* __restrict__ Al,
              int sA,
              const __nv_bfloat16* __restrict__ Bh, const __nv_bfloat16* __restrict__ Bl,
              const float* __restrict__ bias,
              float* __restrict__ Cf, __nv_bfloat16* __restrict__ Ch, __nv_bfloat16* __restrict__ Cl,
              int K, int nch, int N, int Nbias, int sC)
{
    extern __shared__ char smem[];
    const uint32_t sb = smem_u32(smem);
    const int tid  = threadIdx.x;
    const int lane = tid & 31;
    const int wid  = tid >> 5;
    const int wrow = wid & 3;        // 0..3 : 32-row group
    const int wcol = wid >> 2;       // 0..1 : 32-col group
    const int row0 = blockIdx.y * 128;
    const int col0 = blockIdx.x * 64;
    const int extw = (N - col0) - wcol * 32;
    const int live_nt = max(0, min(4, (extw + 7) >> 3));
    const int kp = nch * 32;

    float acc[2][4][4];
    #pragma unroll
    for (int i = 0; i < 2; i++)
        #pragma unroll
        for (int j = 0; j < 4; j++)
            #pragma unroll
            for (int q = 0; q < 4; q++) acc[i][j][q] = 0.f;

    auto load_chunk = [&](int c, int s) {
        const uint32_t stb = sb + s * ST_SZ;
        // B: 64 rows x 64B x2 arrays; 2 cp16/thread; gmem fully zero-padded
        {
            const int br = tid >> 2;           // 0..63
            const int bq = tid & 3;            // 16B chunk
            uint32_t d = stb + br * 80 + bq * 16;
            size_t g = (size_t)(col0 + br) * kp + c * 32 + bq * 8;
            cp16(d + BHI_O, Bh + g, 16);
            cp16(d + BLO_O, Bl + g, 16);
        }
        if (A_PRE) {
            // A: 128 rows x 64B x2 arrays; 4 cp16/thread with K zfill guards
            const int ar = tid >> 1;           // 0..127
            const int ah2 = (tid & 1) * 2;     // chunk pair 0-1 or 2-3
            int k0 = c * 32 + ah2 * 8;
            uint32_t d = stb + ar * 80 + ah2 * 16;
            size_t g = (size_t)(row0 + ar) * sA + k0;
            int s0 = min(16, max(0, (K - k0) * 2));
            int s1 = min(16, max(0, (K - (k0 + 8)) * 2));
            cp16(d + AHI_O,      Ah + g,     s0);
            cp16(d + AHI_O + 16, Ah + g + 8, s1);
            cp16(d + ALO_O,      Al + g,     s0);
            cp16(d + ALO_O + 16, Al + g + 8, s1);
        } else {
            // fp32 A: load, split, plain smem store (16 elems/thread)
            const int ar  = tid >> 1;
            const int akh = (tid & 1) * 16;
            uint32_t hw[8], lw[8];
            #pragma unroll
            for (int i = 0; i < 4; ++i) {
                int k = c * 32 + akh + i * 4;
                float4 v = make_float4(0.f, 0.f, 0.f, 0.f);
                if (k < K) v = *(const float4*)(Af + (size_t)(row0 + ar) * K + k);
                __nv_bfloat16 h0, l0, h1, l1;
                split_bf16(v.x, h0, l0); split_bf16(v.y, h1, l1);
                hw[i*2]   = pack_us(h0, h1); lw[i*2]   = pack_us(l0, l1);
                split_bf16(v.z, h0, l0); split_bf16(v.w, h1, l1);
                hw[i*2+1] = pack_us(h0, h1); lw[i*2+1] = pack_us(l0, l1);
            }
            char* d = smem + s * ST_SZ + ar * 80 + akh * 2;
            *(uint4*)(d + AHI_O)      = make_uint4(hw[0], hw[1], hw[2], hw[3]);
            *(uint4*)(d + AHI_O + 16) = make_uint4(hw[4], hw[5], hw[6], hw[7]);
            *(uint4*)(d + ALO_O)      = make_uint4(lw[0], lw[1], lw[2], lw[3]);
            *(uint4*)(d + ALO_O + 16) = make_uint4(lw[4], lw[5], lw[6], lw[7]);
        }
    };

    // prologue: chunks 0, 1 into stages 0, 1
    load_chunk(0, 0); CP_COMMIT();
    load_chunk(1, 1); CP_COMMIT();

    for (int c = 0; c < nch; ++c) {
        CP_WAIT1();            // chunk c's group complete
        __syncthreads();       // all warps: chunk c visible, compute(c-1) done
        if (c + 2 < nch) load_chunk(c + 2, (c + 2) % 3);
        CP_COMMIT();           // commit every iter to keep group counting uniform

        const uint32_t stb = sb + (c % 3) * ST_SZ;
        #pragma unroll
        for (int ks = 0; ks < 2; ++ks) {
            uint32_t bh[8], bl[8];
            #pragma unroll
            for (int p = 0; p < 2; ++p) {
                uint32_t n = wcol * 32 + p * 16 + (lane & 7) + ((lane >> 4) << 3);
                uint32_t off = n * 80 + ((lane >> 3) & 1) * 16 + ks * 32;
                ldsm4(&bh[p * 4], stb + BHI_O + off);
                ldsm4(&bl[p * 4], stb + BLO_O + off);
            }
            #pragma unroll
            for (int mt = 0; mt < 2; ++mt) {
                uint32_t r = wrow * 32 + mt * 16 + (lane & 15);
                uint32_t off = r * 80 + ((lane >> 4) << 4) + ks * 32;
                uint32_t ah[4], al[4];
                ldsm4(ah, stb + AHI_O + off);
                ldsm4(al, stb + ALO_O + off);
                #pragma unroll
                for (int nt = 0; nt < 4; ++nt) {
                    if (nt < live_nt) {
                        mma_bf16(acc[mt][nt], ah, &bh[nt * 2]);
                        mma_bf16(acc[mt][nt], ah, &bl[nt * 2]);
                        mma_bf16(acc[mt][nt], al, &bh[nt * 2]);
                    }
                }
            }
        }
    }

    // ---- store ----
    #pragma unroll
    for (int mt = 0; mt < 2; ++mt) {
        int r0 = row0 + wrow * 32 + mt * 16 + (lane >> 2);
        int r1 = r0 + 8;
        #pragma unroll
        for (int nt = 0; nt < 4; ++nt) {
            int col = col0 + wcol * 32 + nt * 8 + (lane & 3) * 2;
            if (OUT_BF16) {
                if (col < N) {
                    float b0 = bias[col], b1 = bias[col + 1];
                    float v00 = fmaxf(acc[mt][nt][0] + b0, 0.f);
                    float v01 = fmaxf(acc[mt][nt][1] + b1, 0.f);
                    float v10 = fmaxf(acc[mt][nt][2] + b0, 0.f);
                    float v11 = fmaxf(acc[mt][nt][3] + b1, 0.f);
                    __nv_bfloat16 h0, l0, h1, l1;
                    split_bf16(v00, h0, l0); split_bf16(v01, h1, l1);
                    *(uint32_t*)(Ch + (size_t)r0 * sC + col) = pack_us(h0, h1);
                    *(uint32_t*)(Cl + (size_t)r0 * sC + col) = pack_us(l0, l1);
                    split_bf16(v10, h0, l0); split_bf16(v11, h1, l1);
                    *(uint32_t*)(Ch + (size_t)r1 * sC + col) = pack_us(h0, h1);
                    *(uint32_t*)(Cl + (size_t)r1 * sC + col) = pack_us(l0, l1);
                }
            } else {
                float b0 = (col < Nbias) ? bias[col] : 0.f;
                float b1 = (col + 1 < Nbias) ? bias[col + 1] : 0.f;
                float2 p0 = make_float2(acc[mt][nt][0] + b0, acc[mt][nt][1] + b1);
                float2 p1 = make_float2(acc[mt][nt][2] + b0, acc[mt][nt][3] + b1);
                *(float2*)(Cf + (size_t)r0 * sC + col) = p0;
                *(float2*)(Cf + (size_t)r1 * sC + col) = p1;
            }
        }
    }
}

// ---------------- math epilogue ----------------
__device__ __forceinline__ float fast_tanh(float x)
{
    float ax = fabsf(x);
    float e  = __expf(-2.f * ax);
    float t  = __fdividef(1.f - e, 1.f + e);
    return copysignf(t, x);
}

__global__ __launch_bounds__(256)
void epilogue_kernel(const float* __restrict__ z3, const float* __restrict__ eps,
                     float* __restrict__ out)
{
    int gwarp = (blockIdx.x * blockDim.x + threadIdx.x) >> 5;
    int lane  = threadIdx.x & 31;
    if (gwarp >= NB) return;

    const float* L = z3 + (size_t)gwarp * 256;

    float term_ttl = 0.f, term_eps = 0.f, corr = 0.f;

    if (lane < A_D) {
        int a = lane;
        float mw[M_D], mm[M_D], lms[M_D];
        #pragma unroll
        for (int m = 0; m < M_D; m++) {
            mw[m]  = fast_tanh(L[a * M_D + m]);
            mm[m]  = fast_tanh(L[85 + a * M_D + m]);
            lms[m] = fast_tanh(L[170 + a * M_D + m]);
        }
        float mx = mw[0];
        #pragma unroll
        for (int m = 1; m < M_D; m++) mx = fmaxf(mx, mw[m]);
        float e[M_D], se = 0.f;
        #pragma unroll
        for (int m = 0; m < M_D; m++) { e[m] = __expf(mw[m] - mx); se += e[m]; }
        float inv = __fdividef(1.f, se);

        float mean = 0.f, alea = 0.f;
        float w[M_D];
        #pragma unroll
        for (int m = 0; m < M_D; m++) {
            w[m]  = e[m] * inv;
            mean += w[m] * mm[m];
            float lc = fminf(fmaxf(lms[m], -10.f), 2.f);
            alea += w[m] * __expf(lc);
        }
        float epis = 0.f;
        #pragma unroll
        for (int m = 0; m < M_D; m++) {
            float dd = mm[m] - mean;
            epis += w[m] * dd * dd;
        }
        epis = fminf(fmaxf(epis, EPIS_MIN), EPIS_MAX);
        float total = alea + epis;

        float ev = eps[(size_t)gwarp * A_D + a];
        float x  = mean + total * ev;
        float th = fast_tanh(x);
        out[(size_t)gwarp * A_D + a] = th;

        float d  = x - mean;
        float zt = __fdividef(d, total);
        float ze = __fdividef(d, epis);
        term_ttl = zt * zt + 2.f * __logf(total);
        term_eps = ze * ze + 2.f * __logf(epis);
        corr     = __logf(1.f - th * th + 1e-6f);
    }

    #pragma unroll
    for (int off = 16; off > 0; off >>= 1) {
        term_ttl += __shfl_down_sync(0xffffffffu, term_ttl, off);
        term_eps += __shfl_down_sync(0xffffffffu, term_eps, off);
        corr     += __shfl_down_sync(0xffffffffu, corr, off);
    }

    if (lane == 0) {
        float lp_ttl = -0.5f * term_ttl - HALF_D_LOG2PI;
        float lp_eps = -0.5f * term_eps - HALF_D_LOG2PI;
        out[(size_t)NB * A_D + gwarp]       = lp_ttl - corr;
        out[(size_t)NB * (A_D + 1) + gwarp] = lp_eps - corr;
    }
}

// ---------------- launch ----------------
extern "C" void kernel_launch(void* const* d_in, const int* in_sizes, int n_in,
                              void* d_out, int out_size)
{
    (void)in_sizes; (void)n_in; (void)out_size;
    const float* state = (const float*)d_in[0];
    const float* eps   = (const float*)d_in[1];
    const float* W1    = (const float*)d_in[2];
    const float* b1    = (const float*)d_in[3];
    const float* W2    = (const float*)d_in[4];
    const float* b2    = (const float*)d_in[5];
    const float* W3    = (const float*)d_in[6];
    const float* b3    = (const float*)d_in[7];
    float* out = (float*)d_out;

    void *p;
    cudaGetSymbolAddress(&p, g_h1hi); __nv_bfloat16* h1h = (__nv_bfloat16*)p;
    cudaGetSymbolAddress(&p, g_h1lo); __nv_bfloat16* h1l = (__nv_bfloat16*)p;
    cudaGetSymbolAddress(&p, g_h2hi); __nv_bfloat16* h2h = (__nv_bfloat16*)p;
    cudaGetSymbolAddress(&p, g_h2lo); __nv_bfloat16* h2l = (__nv_bfloat16*)p;
    cudaGetSymbolAddress(&p, g_z3);   float* z3 = (float*)p;
    cudaGetSymbolAddress(&p, g_w1hi); __nv_bfloat16* w1h = (__nv_bfloat16*)p;
    cudaGetSymbolAddress(&p, g_w1lo); __nv_bfloat16* w1l = (__nv_bfloat16*)p;
    cudaGetSymbolAddress(&p, g_w2hi); __nv_bfloat16* w2h = (__nv_bfloat16*)p;
    cudaGetSymbolAddress(&p, g_w2lo); __nv_bfloat16* w2l = (__nv_bfloat16*)p;
    cudaGetSymbolAddress(&p, g_w3hi); __nv_bfloat16* w3h = (__nv_bfloat16*)p;
    cudaGetSymbolAddress(&p, g_w3lo); __nv_bfloat16* w3l = (__nv_bfloat16*)p;

    cudaFuncSetAttribute(mma_gemm<0,1>, cudaFuncAttributeMaxDynamicSharedMemorySize, SMEM_TOT);
    cudaFuncSetAttribute(mma_gemm<1,1>, cudaFuncAttributeMaxDynamicSharedMemorySize, SMEM_TOT);
    cudaFuncSetAttribute(mma_gemm<1,0>, cudaFuncAttributeMaxDynamicSharedMemorySize, SMEM_TOT);

    // weight prep
    split_w<<<(512 * K1P + 255) / 256, 256>>>(W1, w1h, w1l, K1,  N1,  K1P, 512 * K1P);
    split_w<<<(384 * K2P + 255) / 256, 256>>>(W2, w2h, w2l, N1,  N2,  K2P, 384 * K2P);
    split_w<<<(256 * K3P + 255) / 256, 256>>>(W3, w3h, w3l, N2,  255, K3P, 256 * K3P);

    dim3 blk(256);
    // L1: A=state fp32 (split in-kernel), out bf16 h1 (stride K2P), relu. N tiles of 64.
    mma_gemm<0,1><<<dim3(7, NB/128), blk, SMEM_TOT>>>(
        state, nullptr, nullptr, 0, w1h, w1l, b1,
        nullptr, h1h, h1l, K1, 12, N1, N1, K2P);
    // L2: A=h1 pre-split, out bf16 h2 (stride K3P), relu
    mma_gemm<1,1><<<dim3(5, NB/128), blk, SMEM_TOT>>>(
        nullptr, h1h, h1l, K2P, w2h, w2l, b2,
        nullptr, h2h, h2l, N1, 13, N2, N2, K3P);
    // L3: A=h2 pre-split, out fp32 z3 (stride 256), raw
    mma_gemm<1,0><<<dim3(4, NB/128), blk, SMEM_TOT>>>(
        nullptr, h2h, h2l, K3P, w3h, w3l, b3,
        z3, nullptr, nullptr, N2, 10, 256, 255, 256);

    epilogue_kernel<<<NB/8, 256>>>(z3, eps, out);
}